// round 4
// baseline (speedup 1.0000x reference)
#include <cuda_runtime.h>
#include <math.h>
#include <stdint.h>

#define BS     32
#define TT     20           // targets per batch
#define GW     76           // grid width/height
#define PLANE  (GW*GW)      // 5776
#define CPB    (3*PLANE)    // cells per batch = 17328
#define NBLK   68           // ceil(CPB/256)
#define GRID   (BS*NBLK)    // 2176
#define NC     80
#define NBANK  64

// scaled anchors = ANCHORS / 8
__constant__ float c_aw9[9] = {1.5f, 2.375f, 5.0f, 4.5f, 9.5f, 9.0f, 17.75f, 24.0f, 57.375f};
__constant__ float c_ah9[9] = {2.0f, 4.5f,  3.5f, 9.375f, 6.875f, 18.25f, 13.75f, 30.375f, 50.125f};
// level-2 anchors (mask [0,1,2])
__constant__ float c_aw3[3] = {1.5f, 2.375f, 5.0f};
__constant__ float c_ah3[3] = {2.0f, 4.5f,  3.5f};

// persistent accumulators: zero-initialized at module load; the finalizing
// block resets them to zero after use so every launch/replay starts clean.
__device__ double       g_accb[NBANK][5];  // 0:loc 1:nobj 2:cls 3:conf 4:mask
__device__ unsigned int g_done;

// softplus(z) = max(z,0)+log1p(exp(-|z|)) == -log(sigmoid(-z)); matches the
// clipped BCE exactly for |z| < 16.1 (clip never binds at these input scales)
__device__ __forceinline__ float softplusf_(float z) {
    float az = fabsf(z);
    return fmaxf(z, 0.0f) + __logf(1.0f + __expf(-az));
}
__device__ __forceinline__ float sigmoidf_(float x) {
    return __fdividef(1.0f, 1.0f + __expf(-x));
}

__global__ void __launch_bounds__(256) k_all(const float* __restrict__ in,
                                             const float* __restrict__ tgt,
                                             float* __restrict__ out)
{
    __shared__ float4 s_box[TT];   // x0,y0,x1,y1 (gt corners)
    __shared__ float4 s_gt[TT];    // gx,gy,gw,gh
    __shared__ float  s_ar[TT];    // gw*gh
    __shared__ int    s_cell[TT];  // a*PLANE + gj*GW + gi, or -1
    __shared__ int    s_gc[TT];    // class index

    const int b   = blockIdx.x / NBLK;
    const int tid = threadIdx.x;
    const int c   = (blockIdx.x % NBLK) * 256 + tid;

    // ---- per-block target prep (cheap, targets are L2-resident broadcast) ----
    if (tid < TT) {
        const float* p = tgt + (b * TT + tid) * 5;
        float gx = p[0] * (float)GW, gy = p[1] * (float)GW;
        float gw = p[2] * (float)GW, gh = p[3] * (float)GW;
        // argmax wh-IoU over 9 anchors, first-max wins (exact divide: ties matter)
        float bestr = -1e30f; int best = 0;
        #pragma unroll
        for (int n = 0; n < 9; n++) {
            float inter = fminf(gw, c_aw9[n]) * fminf(gh, c_ah9[n]);
            float uni   = gw * gh + c_aw9[n] * c_ah9[n] - inter;
            float r = inter / uni;
            if (r > bestr) { bestr = r; best = n; }
        }
        int cell = -1;
        if (best < 3) {  // l=2: anchors_mask [0,1,2]
            int gi = min(max((int)floorf(gx), 0), GW - 1);
            int gj = min(max((int)floorf(gy), 0), GW - 1);
            cell = best * PLANE + gj * GW + gi;
        }
        s_gt[tid]   = make_float4(gx, gy, gw, gh);
        s_box[tid]  = make_float4(gx - 0.5f * gw, gy - 0.5f * gh,
                                  gx + 0.5f * gw, gy + 0.5f * gh);
        s_ar[tid]   = gw * gh;
        s_cell[tid] = cell;
        s_gc[tid]   = (int)p[4];
    }
    __syncthreads();

    float cl = 0.0f, cm = 0.0f;          // conf BCE sum, conf mask count
    float lloc = 0.0f, lcls = 0.0f, nob = 0.0f;

    if (c < CPB) {
        int a   = c / PLANE;
        int rem = c - a * PLANE;
        int gi = rem % GW;
        int gj = rem / GW;
        const float* base = in + ((b * 255 + a * 85) * PLANE + rem);
        float rx = base[0];
        float ry = base[PLANE];
        float rw = base[2 * PLANE];
        float rh = base[3 * PLANE];
        float rc = base[4 * PLANE];

        float px = (float)gi + sigmoidf_(rx);
        float py = (float)gj + sigmoidf_(ry);
        float pw = __expf(rw) * c_aw3[a];
        float ph = __expf(rh) * c_ah3[a];

        float p0x = px - 0.5f * pw, p1x = px + 0.5f * pw;
        float p0y = py - 0.5f * ph, p1y = py + 0.5f * ph;
        float pa  = pw * ph;

        // combined: ignore margin (iou>0.5 <=> 3*inter > ga+pa) + obj-cell match
        float marg = -1e30f;
        int mt = -1;
        #pragma unroll
        for (int t = 0; t < TT; t++) {
            float4 bb = s_box[t];
            float iw = fmaxf(fminf(bb.z, p1x) - fmaxf(bb.x, p0x), 0.0f);
            float ih = fmaxf(fminf(bb.w, p1y) - fmaxf(bb.y, p0y), 0.0f);
            float inter = iw * ih;
            marg = fmaxf(marg, 3.0f * inter - (s_ar[t] + pa));
            if (s_cell[t] == c) mt = t;
        }
        bool ign = marg > 0.0f;
        bool obj = mt >= 0;

        if (obj) {
            cl = softplusf_(-rc);  cm = 1.0f;   // -log(sigmoid(rc))
        } else if (!ign) {
            cl = softplusf_(rc);   cm = 1.0f;   // -log(1-sigmoid(rc))
        }

        if (obj) {
            // ---- ciou vs matched gt ----
            float4 g = s_gt[mt];
            float gx = g.x, gy = g.y, gw = g.z, gh = g.w;
            float q0x = gx - 0.5f * gw, q1x = gx + 0.5f * gw;
            float q0y = gy - 0.5f * gh, q1y = gy + 0.5f * gh;

            float iw = fmaxf(fminf(p1x, q1x) - fmaxf(p0x, q0x), 0.0f);
            float ih = fmaxf(fminf(p1y, q1y) - fmaxf(p0y, q0y), 0.0f);
            float inter = iw * ih;
            float uni = fmaxf(pa + gw * gh - inter, 1e-6f);
            float iou = inter / uni;

            float dx = px - gx, dy = py - gy;
            float cd = dx * dx + dy * dy;
            float ew = fmaxf(fmaxf(p1x, q1x) - fminf(p0x, q0x), 0.0f);
            float eh = fmaxf(fmaxf(p1y, q1y) - fminf(p0y, q0y), 0.0f);
            float diag = fmaxf(ew * ew + eh * eh, 1e-6f);
            float ciou = iou - cd / diag;

            float dv = atanf(pw / fmaxf(ph, 1e-6f)) - atanf(gw / fmaxf(gh, 1e-6f));
            float v = 0.4052847345693511f * dv * dv;   // 4/pi^2
            float alpha = v / fmaxf(1.0f - iou + v, 1e-6f);
            ciou -= alpha * v;

            lloc = 1.0f - ciou;
            nob  = 1.0f;

            // ---- 80-class BCE (rare thread; loads overlap via unroll MLP) ----
            int gc = s_gc[mt];
            float cls = 0.0f;
            #pragma unroll 8
            for (int ch = 0; ch < NC; ch++) {
                float z = base[(5 + ch) * PLANE];
                cls += (ch == gc) ? softplusf_(-z) : softplusf_(z);
            }
            lcls = cls;
        }
    }

    // ---- block reduction of 5 floats ----
    #pragma unroll
    for (int o = 16; o > 0; o >>= 1) {
        cl   += __shfl_down_sync(0xffffffffu, cl,   o);
        cm   += __shfl_down_sync(0xffffffffu, cm,   o);
        lloc += __shfl_down_sync(0xffffffffu, lloc, o);
        lcls += __shfl_down_sync(0xffffffffu, lcls, o);
        nob  += __shfl_down_sync(0xffffffffu, nob,  o);
    }
    __shared__ float wsum[8][5];
    int wid = tid >> 5;
    if ((tid & 31) == 0) {
        wsum[wid][0] = lloc; wsum[wid][1] = nob; wsum[wid][2] = lcls;
        wsum[wid][3] = cl;   wsum[wid][4] = cm;
    }
    __syncthreads();

    if (tid == 0) {
        float s0=0, s1=0, s2=0, s3=0, s4=0;
        #pragma unroll
        for (int k = 0; k < 8; k++) {
            s0 += wsum[k][0]; s1 += wsum[k][1]; s2 += wsum[k][2];
            s3 += wsum[k][3]; s4 += wsum[k][4];
        }
        int bank = blockIdx.x & (NBANK - 1);
        if (s1 != 0.0f) {  // obj terms present
            atomicAdd(&g_accb[bank][0], (double)s0);
            atomicAdd(&g_accb[bank][1], (double)s1);
            atomicAdd(&g_accb[bank][2], (double)s2);
        }
        atomicAdd(&g_accb[bank][3], (double)s3);
        atomicAdd(&g_accb[bank][4], (double)s4);

        __threadfence();
        unsigned int v = atomicAdd(&g_done, 1u);
        if (v == GRID - 1) {
            // last block: finalize + reset
            __threadfence();
            double a0=0, a1=0, a2=0, a3=0, a4=0;
            for (int k = 0; k < NBANK; k++) {
                a0 += g_accb[k][0]; a1 += g_accb[k][1]; a2 += g_accb[k][2];
                a3 += g_accb[k][3]; a4 += g_accb[k][4];
                g_accb[k][0]=0.0; g_accb[k][1]=0.0; g_accb[k][2]=0.0;
                g_accb[k][3]=0.0; g_accb[k][4]=0.0;
            }
            g_done = 0u;
            double n  = a1 > 1.0 ? a1 : 1.0;
            double cmask = a4 > 1.0 ? a4 : 1.0;
            const double OBJ_RATIO = 5.0 * 608.0 * 608.0 / (416.0 * 416.0);
            const double BAL = 4.0;   // BALANCE[2]
            double loss = a0 / n * 0.05
                        + a2 / (n * (double)NC)
                        + a3 / cmask * BAL * OBJ_RATIO;
            out[0] = (float)loss;
        }
    }
}

extern "C" void kernel_launch(void* const* d_in, const int* in_sizes, int n_in,
                              void* d_out, int out_size) {
    const float* in  = (const float*)d_in[0];
    const float* tgt = (const float*)d_in[1];
    float* out = (float*)d_out;
    k_all<<<GRID, 256>>>(in, tgt, out);
}